// round 16
// baseline (speedup 1.0000x reference)
#include <cuda_runtime.h>
#include <cuda_bf16.h>
#include <math.h>

#define HW_ 16384

// ---------------- scratch (static device globals; no allocation) ----------------
__device__ __nv_bfloat16 g_actvB[4*HW_*128];   // NHWC bf16: [b][y][x][ic]
__device__ __nv_bfloat16 g_wBp[9*128*128];     // [tap][oc][ic] bf16
__device__ float g_noiseT[4*HW_];
__device__ float g_mean[256];
__device__ float g_rstd[256];
__device__ float g_mmu[4*6*512];
__device__ float g_Gg[4*6*576];
__device__ float g_Gb[4*6*576];
__device__ unsigned char g_region[4*HW_];

// ---------------- f32x2 helpers ----------------
__device__ __forceinline__ unsigned long long pk2(float a, float b){
    unsigned long long r; asm("mov.b64 %0, {%1,%2};" : "=l"(r) : "f"(a), "f"(b)); return r;
}
__device__ __forceinline__ void upk2(unsigned long long v, float& a, float& b){
    asm("mov.b64 {%0,%1}, %2;" : "=f"(a), "=f"(b) : "l"(v));
}
__device__ __forceinline__ void add2(unsigned long long& d, unsigned long long a){
    asm("add.rn.f32x2 %0, %1, %2;" : "=l"(d) : "l"(a), "l"(d));
}
__device__ __forceinline__ void fma2(unsigned long long& d, unsigned long long a, unsigned long long b){
    asm("fma.rn.f32x2 %0, %1, %2, %3;" : "=l"(d) : "l"(a), "l"(b), "l"(d));
}

// ---------------- mma / ldmatrix / cp.async helpers (sm_80+ portable) ----------------
__device__ __forceinline__ unsigned smem_u32(const void* p){
    unsigned r; asm("{ .reg .u64 t; cvta.to.shared.u64 t, %1; cvt.u32.u64 %0, t; }" : "=r"(r) : "l"(p));
    return r;
}
__device__ __forceinline__ void ldmx4(unsigned* r, unsigned addr){
    asm volatile("ldmatrix.sync.aligned.m8n8.x4.shared.b16 {%0,%1,%2,%3}, [%4];"
        : "=r"(r[0]),"=r"(r[1]),"=r"(r[2]),"=r"(r[3]) : "r"(addr));
}
__device__ __forceinline__ void mma16816(float* d, const unsigned* a, const unsigned* bq){
    asm volatile("mma.sync.aligned.m16n8k16.row.col.f32.bf16.bf16.f32 "
        "{%0,%1,%2,%3}, {%4,%5,%6,%7}, {%8,%9}, {%0,%1,%2,%3};"
        : "+f"(d[0]),"+f"(d[1]),"+f"(d[2]),"+f"(d[3])
        : "r"(a[0]),"r"(a[1]),"r"(a[2]),"r"(a[3]), "r"(bq[0]),"r"(bq[1]));
}
__device__ __forceinline__ void cpa16(unsigned dst, const void* src){
    asm volatile("cp.async.cg.shared.global [%0], [%1], 16;" :: "r"(dst), "l"(src) : "memory");
}
#define CPA_COMMIT() asm volatile("cp.async.commit_group;" ::: "memory")
#define CPA_WAIT0()  asm volatile("cp.async.wait_group 0;" ::: "memory")

// ---------------- K1: prep = wtrans(0..575) | region(576..831) | noiseT(832..1087) | mmu(1088..1279) ----------------
__global__ void __launch_bounds__(256) fusedprep_kernel(
        const float* __restrict__ swg, const float* __restrict__ swb,
        const float* __restrict__ segmap, const float* __restrict__ noise,
        const float* __restrict__ codes, const float* __restrict__ fcw,
        const float* __restrict__ fcb){
    int blk = blockIdx.x;
    int tid = threadIdx.x;
    if(blk < 576){
        int i = blk*256 + tid;                       // 147456
        int tap = i >> 14; int oc = (i >> 7) & 127; int ic = i & 127;
        float v = (oc < 64) ? swg[(size_t)oc*1152 + ic*9 + tap]
                            : swb[(size_t)(oc-64)*1152 + ic*9 + tap];
        g_wBp[i] = __float2bfloat16(v);
    }else if(blk < 832){
        int i = (blk-576)*256 + tid;                 // 65536
        int b = i >> 14, p = i & 16383;
        unsigned char r = 6;
        #pragma unroll
        for(int j = 0; j < 6; j++)
            if(segmap[((size_t)(b*6+j)<<14) + p] != 0.f) r = (unsigned char)j;
        g_region[i] = r;
    }else if(blk < 1088){
        int i = (blk-832)*256 + tid;                 // 65536
        int b = i >> 14, p = i & 16383;
        int h = p >> 7, w = p & 127;
        g_noiseT[i] = noise[(b<<14) + (w<<7) + h];
    }else{
        // --- middle_mu: 192 blocks = 24 bf x 8 og ---
        int idx = blk - 1088;
        int bf = idx % 24, og = idx / 24;
        int f = bf % 6;
        int lane = tid & 31, warp = tid >> 5;
        float c[16];
        const float4* cp = reinterpret_cast<const float4*>(codes + (size_t)bf*512);
        #pragma unroll
        for(int it=0; it<4; it++){
            float4 v = cp[it*32 + lane];
            c[it*4+0]=v.x; c[it*4+1]=v.y; c[it*4+2]=v.z; c[it*4+3]=v.w;
        }
        #pragma unroll
        for(int r = 0; r < 8; r++){
            int o = og*64 + warp*8 + r;
            const float4* wp = reinterpret_cast<const float4*>(fcw + ((size_t)f*512 + o)*512);
            float s = 0.f;
            #pragma unroll
            for(int it=0; it<4; it++){
                float4 w = wp[it*32 + lane];
                s += w.x*c[it*4] + w.y*c[it*4+1] + w.z*c[it*4+2] + w.w*c[it*4+3];
            }
            #pragma unroll
            for(int st=16; st>0; st>>=1) s += __shfl_xor_sync(0xffffffffu, s, st);
            if(lane==0) g_mmu[bf*512+o] = fmaxf(s + fcb[f*512+o], 0.f);
        }
    }
}

// ---------------- K2: gtab (0..127) | actv (128..383) | stats (384..639) ----------------
#define GTAB_SMEM ((4608 + 12288)*4)
__global__ void __launch_bounds__(256) gtab_actv_stats_kernel(
        const float* __restrict__ wg, const float* __restrict__ wb,
        const float* __restrict__ mask,
        const float* __restrict__ ssw, const float* __restrict__ ssb,
        const float* __restrict__ x, const float* __restrict__ nvar){
    extern __shared__ float gsm[];
    int blk = blockIdx.x;
    int tid = threadIdx.x;
    if(blk < 128){
        float* sw = gsm;
        float* sm = gsm + 4608;
        int table = blk >> 6, oc = blk & 63;
        int lane = tid & 31, warp = tid >> 5;
        const float* w = (table ? wb : wg) + (size_t)oc*4608;
        for(int i = tid; i < 4608; i += 256) sw[i] = w[i];
        for(int i = tid; i < 12288; i += 256) sm[i] = g_mmu[i];
        __syncthreads();
        for(int j = warp*27; j < warp*27 + 27; j++){
            int bf = j / 9, tap = j % 9;
            const float* mrow = &sm[bf*512];
            float acc = 0.f;
            #pragma unroll
            for(int k = 0; k < 16; k++){
                int d = lane + k*32;
                acc += sw[d*9 + tap] * mrow[d];
            }
            #pragma unroll
            for(int st=16; st>0; st>>=1) acc += __shfl_xor_sync(0xffffffffu, acc, st);
            if(lane == 0){
                if(table) g_Gb[bf*576 + tap*64 + oc] = acc;
                else      g_Gg[bf*576 + tap*64 + oc] = acc;
            }
        }
    }else if(blk < 384){
        unsigned long long* sp = reinterpret_cast<unsigned long long*>(gsm);
        float* sbias = reinterpret_cast<float*>(sp + 1728);
        int ab = blk - 128;
        int b = ab >> 6;
        int y = (ab & 63)*2 + (tid >> 7);
        int xx = tid & 127;
        for(int i = tid; i < 1728; i += 256){
            int k = i >> 6, icp = i & 63;
            sp[i] = pk2(ssw[(2*icp)*27 + k], ssw[(2*icp+1)*27 + k]);
        }
        if(tid < 128) sbias[tid] = ssb[tid];
        unsigned long long am[27];
        #pragma unroll
        for(int m = 0; m < 3; m++)
            #pragma unroll
            for(int ky = 0; ky < 3; ky++)
                #pragma unroll
                for(int kx = 0; kx < 3; kx++){
                    int gy = y + ky - 1, gx = xx + kx - 1;
                    float mv = (gy >= 0 && gy < 128 && gx >= 0 && gx < 128)
                        ? mask[((size_t)(b*3+m)<<14) + (gy<<7) + gx] : 0.f;
                    am[m*9 + ky*3 + kx] = pk2(mv, mv);
                }
        __syncthreads();
        unsigned outp[64];
        for(int icp = 0; icp < 64; icp++){
            unsigned long long acc = pk2(sbias[2*icp], sbias[2*icp+1]);
            #pragma unroll
            for(int k = 0; k < 27; k++) fma2(acc, am[k], sp[k*64 + icp]);
            float a0, a1; upk2(acc, a0, a1);
            __nv_bfloat162 h = __floats2bfloat162_rn(fmaxf(a0, 0.f), fmaxf(a1, 0.f));
            outp[icp] = *reinterpret_cast<unsigned*>(&h);
        }
        uint4* dst = reinterpret_cast<uint4*>(g_actvB) + ((size_t)((b<<14) + (y<<7) + xx))*16;
        const uint4* srcp = reinterpret_cast<const uint4*>(outp);
        #pragma unroll
        for(int i = 0; i < 16; i++) dst[i] = srcp[i];
    }else{
        int bc = blk - 384; int b = bc >> 6;
        float nv = nvar[bc & 63];
        const float4* xp = reinterpret_cast<const float4*>(x + (size_t)bc*HW_);
        const float4* np = reinterpret_cast<const float4*>(g_noiseT + ((size_t)b<<14));
        float s = 0.f, ss = 0.f;
        for(int i = tid; i < HW_/4; i += 256){
            float4 xv = xp[i]; float4 nn = np[i];
            float v;
            v = xv.x + nv*nn.x; s += v; ss += v*v;
            v = xv.y + nv*nn.y; s += v; ss += v*v;
            v = xv.z + nv*nn.z; s += v; ss += v*v;
            v = xv.w + nv*nn.w; s += v; ss += v*v;
        }
        float* rs = gsm; float* rq = gsm + 256;
        rs[tid] = s; rq[tid] = ss;
        __syncthreads();
        for(int st = 128; st > 0; st >>= 1){
            if(tid < st){ rs[tid] += rs[tid+st]; rq[tid] += rq[tid+st]; }
            __syncthreads();
        }
        if(tid == 0){
            float m = rs[0]*(1.f/HW_);
            float var = rq[0]*(1.f/HW_) - m*m;
            g_mean[bc] = m;
            g_rstd[bc] = rsqrtf(var + 1e-5f);
        }
    }
}

// ---------------- K3: SPADE conv (2 rows, 512 thr, 64x32 tiles, B direct from L2) + FUSED final ----------------
#define APLANE 17680             // 130*136 elems
#define SPADE_SMEM (132096 + 32768)   // Dsm[256][129] fp32 + G tables; > 4*APLANE*2=141440 -> use 165 KB? no:
// NOTE: A staging needs 4*APLANE*2 = 141440 B; epilogue needs 132096 + 32704 = 164800 B. Take max+pad.
#undef SPADE_SMEM
#define SPADE_SMEM 164864

__global__ void __launch_bounds__(512) spade_fused_kernel(
        const float* __restrict__ x,   const float* __restrict__ nvar,
        const float* __restrict__ sgb, const float* __restrict__ sbb,
        const float* __restrict__ cgb, const float* __restrict__ cbb,
        const float* __restrict__ bg,  const float* __restrict__ bb2,
        float* __restrict__ out){
    extern __shared__ __align__(16) unsigned char dynsm[];
    __nv_bfloat16* sA = reinterpret_cast<__nv_bfloat16*>(dynsm);   // 4 halo planes
    __shared__ float s_bias[128];
    __shared__ float s_mean[64], s_rstd[64], s_nv[64], s_gb[64], s_bb[64];

    int y0 = blockIdx.x*2, b = blockIdx.y;
    int tid = threadIdx.x;
    if(tid < 128) s_bias[tid] = (tid < 64) ? sgb[tid] : sbb[tid-64];
    else if(tid < 192){
        int t = tid - 128;
        s_mean[t] = g_mean[b*64+t]; s_rstd[t] = g_rstd[b*64+t];
        s_nv[t] = nvar[t]; s_gb[t] = cgb[t]; s_bb[t] = cbb[t];
    }

    // --- stage 4 A halo planes (rows y0-1 .. y0+2) + zero borders/OOB ---
    for(int pl = 0; pl < 4; pl++){
        int sr = y0 + pl - 1;
        uint4* plane4 = reinterpret_cast<uint4*>(sA + pl*APLANE);
        if(sr < 0 || sr > 127){
            for(int i = tid; i < 2210; i += 512) plane4[i] = make_uint4(0,0,0,0);
        }else{
            if(tid < 17) plane4[tid] = make_uint4(0,0,0,0);                    // halo px -1
            else if(tid < 34) plane4[129*17 + (tid-17)] = make_uint4(0,0,0,0); // halo px 128
            const __nv_bfloat16* src = g_actvB + ((size_t)((b<<14) + (sr<<7)))*128;
            for(int i = tid; i < 2048; i += 512){
                int px = i >> 4, ch = i & 15;
                cpa16(smem_u32(sA + pl*APLANE + (px+1)*136 + ch*8), src + px*128 + ch*8);
            }
        }
    }
    CPA_COMMIT();
    CPA_WAIT0();
    __syncthreads();

    int lane = tid & 31, warp = tid >> 5;
    int wM = warp & 3, wN = warp >> 2;     // 4 x 4 warp grid: 64px x 32oc per warp
    int rIdx = wM >> 1;
    int pxBase = (wM & 1)*64;
    unsigned sA_u = smem_u32(sA);

    float d[4][4][4];
    #pragma unroll
    for(int mt=0; mt<4; mt++)
        #pragma unroll
        for(int nt=0; nt<4; nt++)
            #pragma unroll
            for(int e=0; e<4; e++) d[mt][nt][e] = 0.f;

    int aRow = (lane & 15);
    int aHalf = (lane >> 4);
    // direct-L2 B fragment addressing: lane l of nt-tile reads
    //   W[wN*32 + nt*8 + (l>>2)][ks*16 + (l&3)*2] and +8
    int bRowOff = (wN*32 + (lane >> 2))*128 + (lane & 3)*2;

    for(int tap = 0; tap < 9; tap++){
        int dy = tap/3, dx = tap%3;
        unsigned aBase = sA_u + (unsigned)((rIdx + dy)*APLANE)*2;
        const __nv_bfloat16* wtap = g_wBp + tap*16384 + bRowOff;
        #pragma unroll
        for(int ks = 0; ks < 8; ks++){
            unsigned a[4][4];
            #pragma unroll
            for(int mt = 0; mt < 4; mt++){
                unsigned ad = aBase + (unsigned)(((pxBase + mt*16 + aRow + dx)*136
                                 + ks*16 + aHalf*8) << 1);
                ldmx4(a[mt], ad);
            }
            unsigned bq[4][2];
            #pragma unroll
            for(int nt = 0; nt < 4; nt++){
                const __nv_bfloat16* wp = wtap + nt*8*128 + ks*16;
                bq[nt][0] = *reinterpret_cast<const unsigned*>(wp);
                bq[nt][1] = *reinterpret_cast<const unsigned*>(wp + 8);
            }
            #pragma unroll
            for(int mt = 0; mt < 4; mt++)
                #pragma unroll
                for(int nt = 0; nt < 4; nt++)
                    mma16816(d[mt][nt], a[mt], bq[nt]);
        }
    }
    __syncthreads();   // all warps done reading sA before Dsm overwrite

    // --- dump D (+spade bias) into smem (reuse A region): Dsm[256][129] fp32 ---
    float* Dsm = reinterpret_cast<float*>(sA);
    #pragma unroll
    for(int mt = 0; mt < 4; mt++){
        int m = wM*64 + mt*16 + (lane >> 2);
        #pragma unroll
        for(int nt = 0; nt < 4; nt++){
            int oc = wN*32 + nt*8 + (lane & 3)*2;
            #pragma unroll
            for(int e = 0; e < 4; e++){
                int mm = m + (e >> 1)*8;
                int o = oc + (e & 1);
                Dsm[mm*129 + o] = d[mt][nt][e] + s_bias[o];
            }
        }
    }
    // --- load G tables into smem (after Dsm region: offset 132096 B) ---
    float* tGg = reinterpret_cast<float*>(dynsm + 132096);
    float* tGb = tGg + 7*584;
    for(int i = tid; i < 7*584; i += 512){
        int r = i/584, k = i%584;
        float vg = 0.f, vb = 0.f;
        if(r < 6 && k < 576){ vg = g_Gg[(b*6+r)*576 + k]; vb = g_Gb[(b*6+r)*576 + k]; }
        tGg[i] = vg; tGb[i] = vb;
    }
    __syncthreads();

    // --- fused final: 512 threads = 2 rows x 128 px x 2 channel-halves ---
    float ga = 1.f/(1.f + expf(-bg[0]));
    float ba = 1.f/(1.f + expf(-bb2[0]));
    int px = tid & 127;
    int half = (tid >> 7) & 1;
    int rr = tid >> 8;
    int y = y0 + rr;
    int base[9];
    #pragma unroll
    for(int tap = 0; tap < 9; tap++){
        int dy = tap/3 - 1, dx = tap%3 - 1;
        int yy = y + dy, xx = px + dx;
        int r = 6;
        if(yy >= 0 && yy < 128 && xx >= 0 && xx < 128) r = g_region[(b<<14) + (yy<<7) + xx];
        base[tap] = r*584 + tap*64;
    }
    float nz = g_noiseT[(b<<14) + (y<<7) + px];
    size_t pix = (size_t)(y<<7) + px;
    int drow = (rr*128 + px)*129;
    for(int jj = 0; jj < 8; jj++){
        int j = half*8 + jj;
        unsigned long long ag0=0ull, ag1=0ull, ab0=0ull, ab1=0ull;
        #pragma unroll
        for(int tap = 0; tap < 9; tap++){
            const ulonglong2* pgp = reinterpret_cast<const ulonglong2*>(&tGg[base[tap] + j*4]);
            const ulonglong2* pbp = reinterpret_cast<const ulonglong2*>(&tGb[base[tap] + j*4]);
            ulonglong2 vg = *pgp, vb = *pbp;
            add2(ag0, vg.x); add2(ag1, vg.y);
            add2(ab0, vb.x); add2(ab1, vb.y);
        }
        float g4[4], b4[4];
        upk2(ag0, g4[0], g4[1]); upk2(ag1, g4[2], g4[3]);
        upk2(ab0, b4[0], b4[1]); upk2(ab1, b4[2], b4[3]);
        #pragma unroll
        for(int k = 0; k < 4; k++){
            int c = j*4 + k;
            size_t idx = (((size_t)(b*64 + c))<<14) + pix;
            float xv = x[idx] + s_nv[c]*nz;
            float xn = (xv - s_mean[c])*s_rstd[c];
            float gf = ga*(g4[k] + s_gb[c]) + (1.f - ga)*Dsm[drow + c];
            float bf = ba*(b4[k] + s_bb[c]) + (1.f - ba)*Dsm[drow + 64 + c];
            out[idx] = xn*(1.f + gf) + bf;
        }
    }
}

extern "C" void kernel_launch(void* const* d_in, const int* in_sizes, int n_in,
                              void* d_out, int out_size) {
    const float* x      = (const float*)d_in[0];
    const float* segmap = (const float*)d_in[1];
    const float* mask   = (const float*)d_in[2];
    const float* codes  = (const float*)d_in[3];
    const float* noise  = (const float*)d_in[4];
    const float* nvar   = (const float*)d_in[5];
    const float* fc_w   = (const float*)d_in[6];
    const float* fc_b   = (const float*)d_in[7];
    const float* cg_w   = (const float*)d_in[8];
    const float* cg_b   = (const float*)d_in[9];
    const float* cb_w   = (const float*)d_in[10];
    const float* cb_b   = (const float*)d_in[11];
    const float* ss_w   = (const float*)d_in[12];
    const float* ss_b   = (const float*)d_in[13];
    const float* sg_w   = (const float*)d_in[14];
    const float* sg_b   = (const float*)d_in[15];
    const float* sb_w   = (const float*)d_in[16];
    const float* sb_b   = (const float*)d_in[17];
    const float* bgam   = (const float*)d_in[18];
    const float* bbet   = (const float*)d_in[19];
    float* out = (float*)d_out;

    cudaFuncSetAttribute(spade_fused_kernel,
                         cudaFuncAttributeMaxDynamicSharedMemorySize, SPADE_SMEM);
    cudaFuncSetAttribute(gtab_actv_stats_kernel,
                         cudaFuncAttributeMaxDynamicSharedMemorySize, GTAB_SMEM);

    fusedprep_kernel<<<1280, 256>>>(sg_w, sb_w, segmap, noise, codes, fc_w, fc_b);
    gtab_actv_stats_kernel<<<640, 256, GTAB_SMEM>>>(cg_w, cb_w, mask, ss_w, ss_b, x, nvar);
    spade_fused_kernel<<<dim3(64,4), 512, SPADE_SMEM>>>(
        x, nvar, sg_b, sb_b, cg_b, cb_b, bgam, bbet, out);
}

// round 17
// speedup vs baseline: 1.3940x; 1.3940x over previous
#include <cuda_runtime.h>
#include <cuda_bf16.h>
#include <math.h>

#define HW_ 16384

// ---------------- scratch (static device globals; no allocation) ----------------
__device__ __nv_bfloat16 g_actvB[4*HW_*128];   // NHWC bf16: [b][y][x][ic]
__device__ __nv_bfloat16 g_wBp[9*128*128];     // [tap][oc][ic] bf16
__device__ float g_noiseT[4*HW_];
__device__ float g_ps[512];                    // per-(b,c,half) partial sum
__device__ float g_pss[512];                   // per-(b,c,half) partial sumsq
__device__ float g_mmu[4*6*512];
__device__ float g_Gg[4*6*576];
__device__ float g_Gb[4*6*576];
__device__ unsigned char g_region[4*HW_];

// ---------------- f32x2 helpers ----------------
__device__ __forceinline__ unsigned long long pk2(float a, float b){
    unsigned long long r; asm("mov.b64 %0, {%1,%2};" : "=l"(r) : "f"(a), "f"(b)); return r;
}
__device__ __forceinline__ void upk2(unsigned long long v, float& a, float& b){
    asm("mov.b64 {%0,%1}, %2;" : "=f"(a), "=f"(b) : "l"(v));
}
__device__ __forceinline__ void add2(unsigned long long& d, unsigned long long a){
    asm("add.rn.f32x2 %0, %1, %2;" : "=l"(d) : "l"(a), "l"(d));
}
__device__ __forceinline__ void fma2(unsigned long long& d, unsigned long long a, unsigned long long b){
    asm("fma.rn.f32x2 %0, %1, %2, %3;" : "=l"(d) : "l"(a), "l"(b), "l"(d));
}

// ---------------- mma / ldmatrix / cp.async helpers (sm_80+ portable) ----------------
__device__ __forceinline__ unsigned smem_u32(const void* p){
    unsigned r; asm("{ .reg .u64 t; cvta.to.shared.u64 t, %1; cvt.u32.u64 %0, t; }" : "=r"(r) : "l"(p));
    return r;
}
__device__ __forceinline__ void ldmx4(unsigned* r, unsigned addr){
    asm volatile("ldmatrix.sync.aligned.m8n8.x4.shared.b16 {%0,%1,%2,%3}, [%4];"
        : "=r"(r[0]),"=r"(r[1]),"=r"(r[2]),"=r"(r[3]) : "r"(addr));
}
__device__ __forceinline__ void mma16816(float* d, const unsigned* a, const unsigned* bq){
    asm volatile("mma.sync.aligned.m16n8k16.row.col.f32.bf16.bf16.f32 "
        "{%0,%1,%2,%3}, {%4,%5,%6,%7}, {%8,%9}, {%0,%1,%2,%3};"
        : "+f"(d[0]),"+f"(d[1]),"+f"(d[2]),"+f"(d[3])
        : "r"(a[0]),"r"(a[1]),"r"(a[2]),"r"(a[3]), "r"(bq[0]),"r"(bq[1]));
}
__device__ __forceinline__ void cpa16(unsigned dst, const void* src){
    asm volatile("cp.async.cg.shared.global [%0], [%1], 16;" :: "r"(dst), "l"(src) : "memory");
}
#define CPA_COMMIT() asm volatile("cp.async.commit_group;" ::: "memory")
#define CPA_WAIT0()  asm volatile("cp.async.wait_group 0;" ::: "memory")

// ---------------- K1: prep = wtrans(0..575) | region(576..831) | noiseT(832..1087) | mmu(1088..1279) ----------------
__global__ void __launch_bounds__(256) fusedprep_kernel(
        const float* __restrict__ swg, const float* __restrict__ swb,
        const float* __restrict__ segmap, const float* __restrict__ noise,
        const float* __restrict__ codes, const float* __restrict__ fcw,
        const float* __restrict__ fcb){
    int blk = blockIdx.x;
    int tid = threadIdx.x;
    if(blk < 576){
        int i = blk*256 + tid;                       // 147456
        int tap = i >> 14; int oc = (i >> 7) & 127; int ic = i & 127;
        float v = (oc < 64) ? swg[(size_t)oc*1152 + ic*9 + tap]
                            : swb[(size_t)(oc-64)*1152 + ic*9 + tap];
        g_wBp[i] = __float2bfloat16(v);
    }else if(blk < 832){
        int i = (blk-576)*256 + tid;                 // 65536
        int b = i >> 14, p = i & 16383;
        unsigned char r = 6;
        #pragma unroll
        for(int j = 0; j < 6; j++)
            if(segmap[((size_t)(b*6+j)<<14) + p] != 0.f) r = (unsigned char)j;
        g_region[i] = r;
    }else if(blk < 1088){
        int i = (blk-832)*256 + tid;                 // 65536
        int b = i >> 14, p = i & 16383;
        int h = p >> 7, w = p & 127;
        g_noiseT[i] = noise[(b<<14) + (w<<7) + h];
    }else{
        // --- middle_mu: 192 blocks = 24 bf x 8 og ---
        int idx = blk - 1088;
        int bf = idx % 24, og = idx / 24;
        int f = bf % 6;
        int lane = tid & 31, warp = tid >> 5;
        float c[16];
        const float4* cp = reinterpret_cast<const float4*>(codes + (size_t)bf*512);
        #pragma unroll
        for(int it=0; it<4; it++){
            float4 v = cp[it*32 + lane];
            c[it*4+0]=v.x; c[it*4+1]=v.y; c[it*4+2]=v.z; c[it*4+3]=v.w;
        }
        #pragma unroll
        for(int r = 0; r < 8; r++){
            int o = og*64 + warp*8 + r;
            const float4* wp = reinterpret_cast<const float4*>(fcw + ((size_t)f*512 + o)*512);
            float s = 0.f;
            #pragma unroll
            for(int it=0; it<4; it++){
                float4 w = wp[it*32 + lane];
                s += w.x*c[it*4] + w.y*c[it*4+1] + w.z*c[it*4+2] + w.w*c[it*4+3];
            }
            #pragma unroll
            for(int st=16; st>0; st>>=1) s += __shfl_xor_sync(0xffffffffu, s, st);
            if(lane==0) g_mmu[bf*512+o] = fmaxf(s + fcb[f*512+o], 0.f);
        }
    }
}

// ---------------- K2: gtab (0..127) | actv (128..383) | stats-halves (384..895) ----------------
#define GTAB_SMEM ((4608 + 12288)*4)
__global__ void __launch_bounds__(256) gtab_actv_stats_kernel(
        const float* __restrict__ wg, const float* __restrict__ wb,
        const float* __restrict__ mask,
        const float* __restrict__ ssw, const float* __restrict__ ssb,
        const float* __restrict__ x, const float* __restrict__ nvar){
    extern __shared__ float gsm[];
    int blk = blockIdx.x;
    int tid = threadIdx.x;
    if(blk < 128){
        float* sw = gsm;
        float* sm = gsm + 4608;
        int table = blk >> 6, oc = blk & 63;
        int lane = tid & 31, warp = tid >> 5;
        const float* w = (table ? wb : wg) + (size_t)oc*4608;
        for(int i = tid; i < 4608; i += 256) sw[i] = w[i];
        for(int i = tid; i < 12288; i += 256) sm[i] = g_mmu[i];
        __syncthreads();
        for(int j = warp*27; j < warp*27 + 27; j++){
            int bf = j / 9, tap = j % 9;
            const float* mrow = &sm[bf*512];
            float acc = 0.f;
            #pragma unroll
            for(int k = 0; k < 16; k++){
                int d = lane + k*32;
                acc += sw[d*9 + tap] * mrow[d];
            }
            #pragma unroll
            for(int st=16; st>0; st>>=1) acc += __shfl_xor_sync(0xffffffffu, acc, st);
            if(lane == 0){
                if(table) g_Gb[bf*576 + tap*64 + oc] = acc;
                else      g_Gg[bf*576 + tap*64 + oc] = acc;
            }
        }
    }else if(blk < 384){
        unsigned long long* sp = reinterpret_cast<unsigned long long*>(gsm);
        float* sbias = reinterpret_cast<float*>(sp + 1728);
        int ab = blk - 128;
        int b = ab >> 6;
        int y = (ab & 63)*2 + (tid >> 7);
        int xx = tid & 127;
        for(int i = tid; i < 1728; i += 256){
            int k = i >> 6, icp = i & 63;
            sp[i] = pk2(ssw[(2*icp)*27 + k], ssw[(2*icp+1)*27 + k]);
        }
        if(tid < 128) sbias[tid] = ssb[tid];
        unsigned long long am[27];
        #pragma unroll
        for(int m = 0; m < 3; m++)
            #pragma unroll
            for(int ky = 0; ky < 3; ky++)
                #pragma unroll
                for(int kx = 0; kx < 3; kx++){
                    int gy = y + ky - 1, gx = xx + kx - 1;
                    float mv = (gy >= 0 && gy < 128 && gx >= 0 && gx < 128)
                        ? mask[((size_t)(b*3+m)<<14) + (gy<<7) + gx] : 0.f;
                    am[m*9 + ky*3 + kx] = pk2(mv, mv);
                }
        __syncthreads();
        unsigned outp[64];
        for(int icp = 0; icp < 64; icp++){
            unsigned long long acc = pk2(sbias[2*icp], sbias[2*icp+1]);
            #pragma unroll
            for(int k = 0; k < 27; k++) fma2(acc, am[k], sp[k*64 + icp]);
            float a0, a1; upk2(acc, a0, a1);
            __nv_bfloat162 h = __floats2bfloat162_rn(fmaxf(a0, 0.f), fmaxf(a1, 0.f));
            outp[icp] = *reinterpret_cast<unsigned*>(&h);
        }
        uint4* dst = reinterpret_cast<uint4*>(g_actvB) + ((size_t)((b<<14) + (y<<7) + xx))*16;
        const uint4* srcp = reinterpret_cast<const uint4*>(outp);
        #pragma unroll
        for(int i = 0; i < 16; i++) dst[i] = srcp[i];
    }else{
        // --- stats partials: 512 blocks, each reduces half of one (b,c) plane ---
        int sid = blk - 384;                 // 0..511
        int bc = sid >> 1, halfsel = sid & 1;
        int b = bc >> 6;
        float nv = nvar[bc & 63];
        const float4* xp = reinterpret_cast<const float4*>(x + (size_t)bc*HW_);
        const float4* np = reinterpret_cast<const float4*>(g_noiseT + ((size_t)b<<14));
        int i0 = halfsel*2048;
        float s = 0.f, ss = 0.f;
        for(int i = i0 + tid; i < i0 + 2048; i += 256){
            float4 xv = xp[i]; float4 nn = np[i];
            float v;
            v = xv.x + nv*nn.x; s += v; ss += v*v;
            v = xv.y + nv*nn.y; s += v; ss += v*v;
            v = xv.z + nv*nn.z; s += v; ss += v*v;
            v = xv.w + nv*nn.w; s += v; ss += v*v;
        }
        float* rs = gsm; float* rq = gsm + 256;
        rs[tid] = s; rq[tid] = ss;
        __syncthreads();
        for(int st = 128; st > 0; st >>= 1){
            if(tid < st){ rs[tid] += rs[tid+st]; rq[tid] += rq[tid+st]; }
            __syncthreads();
        }
        if(tid == 0){ g_ps[sid] = rs[0]; g_pss[sid] = rq[0]; }
    }
}

// ---------------- K3: SPADE conv (R14 config, frozen) + FUSED final ----------------
#define APLANE 17680             // 130*136 elems
#define WBUF   17408             // 128*136 elems
#define SPADE_SMEM ((4*APLANE + 2*WBUF)*2)

__global__ void __launch_bounds__(512) spade_fused_kernel(
        const float* __restrict__ x,   const float* __restrict__ nvar,
        const float* __restrict__ sgb, const float* __restrict__ sbb,
        const float* __restrict__ cgb, const float* __restrict__ cbb,
        const float* __restrict__ bg,  const float* __restrict__ bb2,
        float* __restrict__ out){
    extern __shared__ __align__(16) unsigned char dynsm[];
    __nv_bfloat16* sA = reinterpret_cast<__nv_bfloat16*>(dynsm);   // 4 halo planes
    __nv_bfloat16* sW = sA + 4*APLANE;
    __shared__ float s_bias[128];
    __shared__ float s_mean[64], s_rstd[64], s_nv[64], s_gb[64], s_bb[64];

    int y0 = blockIdx.x*2, b = blockIdx.y;
    int tid = threadIdx.x;
    if(tid < 128) s_bias[tid] = (tid < 64) ? sgb[tid] : sbb[tid-64];
    else if(tid < 192){
        int t = tid - 128;
        int bc = b*64 + t;
        float s  = g_ps[bc*2]  + g_ps[bc*2+1];
        float ss = g_pss[bc*2] + g_pss[bc*2+1];
        float m = s*(1.f/HW_);
        float var = ss*(1.f/HW_) - m*m;
        s_mean[t] = m;
        s_rstd[t] = rsqrtf(var + 1e-5f);
        s_nv[t] = nvar[t]; s_gb[t] = cgb[t]; s_bb[t] = cbb[t];
    }

    // --- stage 4 A halo planes (rows y0-1 .. y0+2) + zero borders/OOB ---
    for(int pl = 0; pl < 4; pl++){
        int sr = y0 + pl - 1;
        uint4* plane4 = reinterpret_cast<uint4*>(sA + pl*APLANE);
        if(sr < 0 || sr > 127){
            for(int i = tid; i < 2210; i += 512) plane4[i] = make_uint4(0,0,0,0);
        }else{
            if(tid < 17) plane4[tid] = make_uint4(0,0,0,0);                    // halo px -1
            else if(tid < 34) plane4[129*17 + (tid-17)] = make_uint4(0,0,0,0); // halo px 128
            const __nv_bfloat16* src = g_actvB + ((size_t)((b<<14) + (sr<<7)))*128;
            for(int i = tid; i < 2048; i += 512){
                int px = i >> 4, ch = i & 15;
                cpa16(smem_u32(sA + pl*APLANE + (px+1)*136 + ch*8), src + px*128 + ch*8);
            }
        }
    }
    // --- prefetch W tap 0 ---
    for(int i = tid; i < 2048; i += 512){
        int n = i >> 4, ch = i & 15;
        cpa16(smem_u32(sW + n*136 + ch*8), g_wBp + n*128 + ch*8);
    }
    CPA_COMMIT();
    CPA_WAIT0();
    __syncthreads();

    int lane = tid & 31, warp = tid >> 5;
    int wM = warp & 3, wN = warp >> 2;     // 4 x 4 warp grid: 64px x 32oc per warp
    int rIdx = wM >> 1;
    int pxBase = (wM & 1)*64;
    unsigned sA_u = smem_u32(sA);
    unsigned sW_u = smem_u32(sW);

    float d[4][4][4];
    #pragma unroll
    for(int mt=0; mt<4; mt++)
        #pragma unroll
        for(int nt=0; nt<4; nt++)
            #pragma unroll
            for(int e=0; e<4; e++) d[mt][nt][e] = 0.f;

    int aRow = (lane & 15);
    int aHalf = (lane >> 4);
    int bMi = lane >> 3;                   // 0..3 matrix index for B ldmx4
    int bR = lane & 7;

    for(int tap = 0; tap < 9; tap++){
        if(tap < 8){
            const __nv_bfloat16* src = g_wBp + (tap+1)*16384;
            __nv_bfloat16* dstb = sW + ((tap+1) & 1)*WBUF;
            for(int i = tid; i < 2048; i += 512){
                int n = i >> 4, ch = i & 15;
                cpa16(smem_u32(dstb + n*136 + ch*8), src + n*128 + ch*8);
            }
            CPA_COMMIT();
        }
        int dy = tap/3, dx = tap%3;
        unsigned aBase = sA_u + (unsigned)((rIdx + dy)*APLANE)*2;
        unsigned wBase = sW_u + (unsigned)((tap & 1)*WBUF)*2;
        #pragma unroll
        for(int ks = 0; ks < 8; ks++){
            unsigned a[4][4];
            #pragma unroll
            for(int mt = 0; mt < 4; mt++){
                unsigned ad = aBase + (unsigned)(((pxBase + mt*16 + aRow + dx)*136
                                 + ks*16 + aHalf*8) << 1);
                ldmx4(a[mt], ad);
            }
            unsigned bq[4][2];
            #pragma unroll
            for(int ntp = 0; ntp < 2; ntp++){
                unsigned bd = wBase + (unsigned)(((wN*32 + ntp*16 + (bMi>>1)*8 + bR)*136
                                 + ks*16 + (bMi&1)*8) << 1);
                unsigned t4[4]; ldmx4(t4, bd);
                bq[2*ntp][0]=t4[0]; bq[2*ntp][1]=t4[1];
                bq[2*ntp+1][0]=t4[2]; bq[2*ntp+1][1]=t4[3];
            }
            #pragma unroll
            for(int mt = 0; mt < 4; mt++)
                #pragma unroll
                for(int nt = 0; nt < 4; nt++)
                    mma16816(d[mt][nt], a[mt], bq[nt]);
        }
        CPA_WAIT0();
        __syncthreads();
    }

    // --- dump D (+spade bias) into smem (reuse A region): Dsm[256][129] fp32 ---
    float* Dsm = reinterpret_cast<float*>(sA);
    #pragma unroll
    for(int mt = 0; mt < 4; mt++){
        int m = wM*64 + mt*16 + (lane >> 2);
        #pragma unroll
        for(int nt = 0; nt < 4; nt++){
            int oc = wN*32 + nt*8 + (lane & 3)*2;
            #pragma unroll
            for(int e = 0; e < 4; e++){
                int mm = m + (e >> 1)*8;
                int o = oc + (e & 1);
                Dsm[mm*129 + o] = d[mt][nt][e] + s_bias[o];
            }
        }
    }
    // --- load G tables into smem (reuse W region) ---
    float* tGg = reinterpret_cast<float*>(sW);
    float* tGb = tGg + 7*584;
    for(int i = tid; i < 7*584; i += 512){
        int r = i/584, k = i%584;
        float vg = 0.f, vb = 0.f;
        if(r < 6 && k < 576){ vg = g_Gg[(b*6+r)*576 + k]; vb = g_Gb[(b*6+r)*576 + k]; }
        tGg[i] = vg; tGb[i] = vb;
    }
    __syncthreads();

    // --- fused final: 512 threads = 2 rows x 128 px x 2 channel-halves ---
    float ga = 1.f/(1.f + expf(-bg[0]));
    float ba = 1.f/(1.f + expf(-bb2[0]));
    int px = tid & 127;
    int half = (tid >> 7) & 1;
    int rr = tid >> 8;
    int y = y0 + rr;
    int base[9];
    #pragma unroll
    for(int tap = 0; tap < 9; tap++){
        int dy = tap/3 - 1, dx = tap%3 - 1;
        int yy = y + dy, xx = px + dx;
        int r = 6;
        if(yy >= 0 && yy < 128 && xx >= 0 && xx < 128) r = g_region[(b<<14) + (yy<<7) + xx];
        base[tap] = r*584 + tap*64;
    }
    float nz = g_noiseT[(b<<14) + (y<<7) + px];
    size_t pix = (size_t)(y<<7) + px;
    int drow = (rr*128 + px)*129;
    for(int jj = 0; jj < 8; jj++){
        int j = half*8 + jj;
        unsigned long long ag0=0ull, ag1=0ull, ab0=0ull, ab1=0ull;
        #pragma unroll
        for(int tap = 0; tap < 9; tap++){
            const ulonglong2* pgp = reinterpret_cast<const ulonglong2*>(&tGg[base[tap] + j*4]);
            const ulonglong2* pbp = reinterpret_cast<const ulonglong2*>(&tGb[base[tap] + j*4]);
            ulonglong2 vg = *pgp, vb = *pbp;
            add2(ag0, vg.x); add2(ag1, vg.y);
            add2(ab0, vb.x); add2(ab1, vb.y);
        }
        float g4[4], b4[4];
        upk2(ag0, g4[0], g4[1]); upk2(ag1, g4[2], g4[3]);
        upk2(ab0, b4[0], b4[1]); upk2(ab1, b4[2], b4[3]);
        #pragma unroll
        for(int k = 0; k < 4; k++){
            int c = j*4 + k;
            size_t idx = (((size_t)(b*64 + c))<<14) + pix;
            float xv = x[idx] + s_nv[c]*nz;
            float xn = (xv - s_mean[c])*s_rstd[c];
            float gf = ga*(g4[k] + s_gb[c]) + (1.f - ga)*Dsm[drow + c];
            float bf = ba*(b4[k] + s_bb[c]) + (1.f - ba)*Dsm[drow + 64 + c];
            out[idx] = xn*(1.f + gf) + bf;
        }
    }
}

extern "C" void kernel_launch(void* const* d_in, const int* in_sizes, int n_in,
                              void* d_out, int out_size) {
    const float* x      = (const float*)d_in[0];
    const float* segmap = (const float*)d_in[1];
    const float* mask   = (const float*)d_in[2];
    const float* codes  = (const float*)d_in[3];
    const float* noise  = (const float*)d_in[4];
    const float* nvar   = (const float*)d_in[5];
    const float* fc_w   = (const float*)d_in[6];
    const float* fc_b   = (const float*)d_in[7];
    const float* cg_w   = (const float*)d_in[8];
    const float* cg_b   = (const float*)d_in[9];
    const float* cb_w   = (const float*)d_in[10];
    const float* cb_b   = (const float*)d_in[11];
    const float* ss_w   = (const float*)d_in[12];
    const float* ss_b   = (const float*)d_in[13];
    const float* sg_w   = (const float*)d_in[14];
    const float* sg_b   = (const float*)d_in[15];
    const float* sb_w   = (const float*)d_in[16];
    const float* sb_b   = (const float*)d_in[17];
    const float* bgam   = (const float*)d_in[18];
    const float* bbet   = (const float*)d_in[19];
    float* out = (float*)d_out;

    cudaFuncSetAttribute(spade_fused_kernel,
                         cudaFuncAttributeMaxDynamicSharedMemorySize, SPADE_SMEM);
    cudaFuncSetAttribute(gtab_actv_stats_kernel,
                         cudaFuncAttributeMaxDynamicSharedMemorySize, GTAB_SMEM);

    fusedprep_kernel<<<1280, 256>>>(sg_w, sb_w, segmap, noise, codes, fc_w, fc_b);
    gtab_actv_stats_kernel<<<896, 256, GTAB_SMEM>>>(cg_w, cb_w, mask, ss_w, ss_b, x, nvar);
    spade_fused_kernel<<<dim3(64,4), 512, SPADE_SMEM>>>(
        x, nvar, sg_b, sb_b, cg_b, cb_b, bgam, bbet, out);
}